// round 3
// baseline (speedup 1.0000x reference)
#include <cuda_runtime.h>

#define BB 32768
#define DD 512
#define EE 10
#define HH 128
#define RH1 256
#define RH2 128

// ---- scratch (static __device__ globals: allocation-guard safe) ----
__device__ float g_hr1[(size_t)BB * RH1];          // 32 MB
__device__ float g_hr2[(size_t)BB * RH2];          // 16 MB
__device__ float g_h1[(size_t)EE * BB * HH];       // 160 MB
__device__ float g_h2[(size_t)EE * BB * HH];       // 160 MB

// ---- packed fp32x2 helpers (FFMA2: only reachable via PTX on sm_103a) ----
__device__ __forceinline__ unsigned long long pk2(float lo, float hi) {
    unsigned long long r;
    asm("mov.b64 %0, {%1, %2};" : "=l"(r) : "f"(lo), "f"(hi));
    return r;
}
__device__ __forceinline__ void upk2(unsigned long long v, float& lo, float& hi) {
    asm("mov.b64 {%0, %1}, %2;" : "=f"(lo), "=f"(hi) : "l"(v));
}
__device__ __forceinline__ void fma2(unsigned long long& acc, unsigned long long a,
                                     unsigned long long b) {
    asm("fma.rn.f32x2 %0, %1, %2, %0;" : "+l"(acc) : "l"(a), "l"(b));
}

// ============================================================================
// Generic tiled GEMM: C[M,N] = act(A[M,K] @ W[K,N] + bias[N]), batched over z.
// Tile 64 rows x 128 cols, 256 threads, 8x4 outputs/thread (2 packed pairs).
// ============================================================================
#define KC 16

__global__ __launch_bounds__(256) void gemm64x128(
    const float* __restrict__ A, const float* __restrict__ W,
    const float* __restrict__ bias, float* __restrict__ C,
    int M, int K, int N,
    long long As, long long Ws, long long Cs, int doRelu)
{
    __shared__ float Xs[KC][68];      // [kk][row], padded
    __shared__ float Wsm[KC][128];    // [kk][col]

    const int e = blockIdx.z;
    A += (long long)e * As;
    W += (long long)e * Ws;
    C += (long long)e * Cs;
    bias += (long long)e * N;

    const int tid = threadIdx.x;
    const int tx = tid & 31, ty = tid >> 5;
    const int row0 = blockIdx.x * 64;
    const int col0 = blockIdx.y * 128;

    unsigned long long acc[8][2];
#pragma unroll
    for (int rr = 0; rr < 8; rr++) { acc[rr][0] = 0ull; acc[rr][1] = 0ull; }

    // A load map: 64 rows x 16 k per chunk; thread -> (row = tid>>2, seg = tid&3)
    const int arow = tid >> 2, aseg = tid & 3;
    const float* Ap = A + (long long)(row0 + arow) * K + aseg * 4;
    // W load map: 2 float4 per thread covering 16 x 128
    const int wkk0 = tid >> 5, wcs = tid & 31;

    const int nk = K / KC;

    float4 pa = *(const float4*)Ap;
    float4 pw0 = *(const float4*)(W + (long long)wkk0 * N + col0 + wcs * 4);
    float4 pw1 = *(const float4*)(W + (long long)(wkk0 + 8) * N + col0 + wcs * 4);

    for (int kc = 0; kc < nk; kc++) {
        // stage current chunk into smem
        Xs[aseg * 4 + 0][arow] = pa.x;
        Xs[aseg * 4 + 1][arow] = pa.y;
        Xs[aseg * 4 + 2][arow] = pa.z;
        Xs[aseg * 4 + 3][arow] = pa.w;
        *(float4*)&Wsm[wkk0][wcs * 4] = pw0;
        *(float4*)&Wsm[wkk0 + 8][wcs * 4] = pw1;
        __syncthreads();

        // prefetch next chunk into registers (latency hidden by compute)
        if (kc + 1 < nk) {
            const int k0 = (kc + 1) * KC;
            pa = *(const float4*)(Ap + k0);
            pw0 = *(const float4*)(W + (long long)(k0 + wkk0) * N + col0 + wcs * 4);
            pw1 = *(const float4*)(W + (long long)(k0 + wkk0 + 8) * N + col0 + wcs * 4);
        }

#pragma unroll
        for (int kk = 0; kk < KC; kk++) {
            const float w0 = Wsm[kk][tx];
            const float w1 = Wsm[kk][tx + 32];
            const float w2 = Wsm[kk][tx + 64];
            const float w3 = Wsm[kk][tx + 96];
            const unsigned long long wp0 = pk2(w0, w1);
            const unsigned long long wp1 = pk2(w2, w3);
#pragma unroll
            for (int rr = 0; rr < 8; rr++) {
                const float x = Xs[kk][ty + 8 * rr];
                const unsigned long long xp = pk2(x, x);
                fma2(acc[rr][0], xp, wp0);
                fma2(acc[rr][1], xp, wp1);
            }
        }
        __syncthreads();
    }

    const float b0 = bias[col0 + tx];
    const float b1 = bias[col0 + tx + 32];
    const float b2 = bias[col0 + tx + 64];
    const float b3 = bias[col0 + tx + 96];

#pragma unroll
    for (int rr = 0; rr < 8; rr++) {
        const long long r = row0 + ty + 8 * rr;
        float c0, c1, c2, c3;
        upk2(acc[rr][0], c0, c1);
        upk2(acc[rr][1], c2, c3);
        c0 += b0; c1 += b1; c2 += b2; c3 += b3;
        if (doRelu) {
            c0 = fmaxf(c0, 0.f); c1 = fmaxf(c1, 0.f);
            c2 = fmaxf(c2, 0.f); c3 = fmaxf(c3, 0.f);
        }
        float* cp = C + r * N + col0 + tx;
        cp[0] = c0; cp[32] = c1; cp[64] = c2; cp[96] = c3;
    }
}

// ============================================================================
// Router layer 3 + gumbel softmax: logits = hr2 @ rw3 + rb3;
// weights = softmax((logits + gumbel(u)) / tau). One thread per row.
// ============================================================================
__global__ __launch_bounds__(256) void router3_kernel(
    const float* __restrict__ hr2, const float* __restrict__ rw3,
    const float* __restrict__ rb3, const float* __restrict__ u,
    float* __restrict__ wout)
{
    __shared__ float w3s[RH2 * EE];
    const int tid = threadIdx.x;
    for (int i = tid; i < RH2 * EE; i += 256) w3s[i] = rw3[i];
    __syncthreads();

    const long long row = (long long)blockIdx.x * 256 + tid;

    float acc[EE];
#pragma unroll
    for (int e = 0; e < EE; e++) acc[e] = rb3[e];

    const float4* hp = (const float4*)(hr2 + row * RH2);
#pragma unroll 8
    for (int k4 = 0; k4 < RH2 / 4; k4++) {
        const float4 h = hp[k4];
        const int k = k4 * 4;
        const float hv[4] = {h.x, h.y, h.z, h.w};
#pragma unroll
        for (int j = 0; j < 4; j++) {
#pragma unroll
            for (int e = 0; e < EE; e++) acc[e] += hv[j] * w3s[(k + j) * EE + e];
        }
    }

    float lg[EE];
    float m = -1e30f;
#pragma unroll
    for (int e = 0; e < EE; e++) {
        float uu = u[row * EE + e];
        uu = fminf(fmaxf(uu, 1e-10f), 1.0f);
        const float g = -logf(-logf(uu) + 1e-10f);
        lg[e] = (acc[e] + g) * (1.0f / 3.0f);
        m = fmaxf(m, lg[e]);
    }
    float s = 0.f;
#pragma unroll
    for (int e = 0; e < EE; e++) { lg[e] = expf(lg[e] - m); s += lg[e]; }
    const float inv = 1.0f / s;
#pragma unroll
    for (int e = 0; e < EE; e++) wout[row * EE + e] = lg[e] * inv;
}

// ============================================================================
// Final: zc = h2 @ ew3 + eb3 -> chart_outputs[E,B,2]; z = sum_e w[b,e]*zc.
// One warp per row b; lanes cover k in float4 chunks; shuffle reduce.
// ============================================================================
__global__ __launch_bounds__(128) void out_kernel(
    const float* __restrict__ h2e, const float* __restrict__ ew3,
    const float* __restrict__ eb3, const float* __restrict__ wts,
    float* __restrict__ z, float* __restrict__ chart)
{
    const int warp = threadIdx.x >> 5, lane = threadIdx.x & 31;
    const long long row = (long long)blockIdx.x * 4 + warp;

    float zz0 = 0.f, zz1 = 0.f;
#pragma unroll
    for (int e = 0; e < EE; e++) {
        const float4 h = *(const float4*)(h2e + ((long long)e * BB + row) * HH + lane * 4);
        const float4 wa = *(const float4*)(ew3 + e * (HH * 2) + lane * 8);
        const float4 wb = *(const float4*)(ew3 + e * (HH * 2) + lane * 8 + 4);
        float p0 = h.x * wa.x + h.y * wa.z + h.z * wb.x + h.w * wb.z;
        float p1 = h.x * wa.y + h.y * wa.w + h.z * wb.y + h.w * wb.w;
#pragma unroll
        for (int o = 16; o; o >>= 1) {
            p0 += __shfl_xor_sync(0xffffffffu, p0, o);
            p1 += __shfl_xor_sync(0xffffffffu, p1, o);
        }
        if (lane == 0) {
            p0 += eb3[e * 2 + 0];
            p1 += eb3[e * 2 + 1];
            chart[((long long)e * BB + row) * 2 + 0] = p0;
            chart[((long long)e * BB + row) * 2 + 1] = p1;
            const float w = wts[row * EE + e];
            zz0 += w * p0;
            zz1 += w * p1;
        }
    }
    if (lane == 0) {
        z[row * 2 + 0] = zz0;
        z[row * 2 + 1] = zz1;
    }
}

// ============================================================================
extern "C" void kernel_launch(void* const* d_in, const int* in_sizes, int n_in,
                              void* d_out, int out_size)
{
    const float* x   = (const float*)d_in[0];
    const float* u   = (const float*)d_in[1];
    const float* rw1 = (const float*)d_in[2];
    const float* rb1 = (const float*)d_in[3];
    const float* rw2 = (const float*)d_in[4];
    const float* rb2 = (const float*)d_in[5];
    const float* rw3 = (const float*)d_in[6];
    const float* rb3 = (const float*)d_in[7];
    const float* ew1 = (const float*)d_in[8];
    const float* eb1 = (const float*)d_in[9];
    const float* ew2 = (const float*)d_in[10];
    const float* eb2 = (const float*)d_in[11];
    const float* ew3 = (const float*)d_in[12];
    const float* eb3 = (const float*)d_in[13];

    float* out   = (float*)d_out;
    float* z     = out;                                 // [B, 2]
    float* wts   = out + (size_t)BB * 2;                // [B, E]
    float* chart = out + (size_t)BB * 2 + (size_t)BB * EE;  // [E, B, 2]

    float *hr1, *hr2, *h1, *h2;
    cudaGetSymbolAddress((void**)&hr1, g_hr1);
    cudaGetSymbolAddress((void**)&hr2, g_hr2);
    cudaGetSymbolAddress((void**)&h1, g_h1);
    cudaGetSymbolAddress((void**)&h2, g_h2);

    // router L1: [B,512] @ [512,256] -> relu -> hr1
    gemm64x128<<<dim3(BB / 64, RH1 / 128, 1), 256>>>(
        x, rw1, rb1, hr1, BB, DD, RH1, 0, 0, 0, 1);
    // router L2: [B,256] @ [256,128] -> relu -> hr2
    gemm64x128<<<dim3(BB / 64, 1, 1), 256>>>(
        hr2 /*dummy*/ == nullptr ? hr1 : hr1, rw2, rb2, hr2, BB, RH1, RH2, 0, 0, 0, 1);
    // router L3 + gumbel softmax -> weights region of d_out
    router3_kernel<<<BB / 256, 256>>>(hr2, rw3, rb3, u, wts);

    // experts L1 (batched over E): [B,512] @ [512,128] -> relu -> h1[e]
    gemm64x128<<<dim3(BB / 64, 1, EE), 256>>>(
        x, ew1, eb1, h1, BB, DD, HH,
        0, (long long)DD * HH, (long long)BB * HH, 1);
    // experts L2: h1[e] @ [128,128] -> relu -> h2[e]
    gemm64x128<<<dim3(BB / 64, 1, EE), 256>>>(
        h1, ew2, eb2, h2, BB, HH, HH,
        (long long)BB * HH, (long long)HH * HH, (long long)BB * HH, 1);

    // experts L3 + weighted combine -> chart + z
    out_kernel<<<BB / 4, 128>>>(h2, ew3, eb3, wts, z, chart);
}

// round 6
// speedup vs baseline: 1.8582x; 1.8582x over previous
#include <cuda_runtime.h>
#include <cstdint>

#define BB 32768
#define DD 512
#define EE 10
#define HH 128
#define RH1 256
#define RH2 128

// ---- scratch (static __device__ globals: allocation-guard safe) ----
__device__ float g_hr1[(size_t)BB * RH1];
__device__ float g_hr2[(size_t)BB * RH2];
__device__ float g_h1[(size_t)EE * BB * HH];
__device__ float g_h2[(size_t)EE * BB * HH];
__device__ float g_xt[(size_t)BB * DD];            // tf32-rounded x
__device__ float g_wr1[(size_t)DD * RH1];          // tf32-rounded weights (orig layout)
__device__ float g_wr2[(size_t)RH1 * RH2];
__device__ float g_we1[(size_t)EE * DD * HH];
__device__ float g_we2[(size_t)EE * HH * HH];

__device__ __forceinline__ float tf32r(float f) {
    float r; asm("cvt.rna.tf32.f32 %0, %1;" : "=f"(r) : "f"(f)); return r;
}
__device__ __forceinline__ uint32_t s2u(const void* p) {
    uint32_t a;
    asm("{ .reg .u64 t; cvta.to.shared.u64 t, %1; cvt.u32.u64 %0, t; }" : "=r"(a) : "l"(p));
    return a;
}

// ---- smem geometry (floats). Padded strides for conflict-free fragment LDS:
//   A bank = (row*36+k)%32 = (row*4+k)%32  -> bijective over (row 0..7, k 0..3)
//   B bank = (k*136+n)%32 = (k*8+n)%32     -> bijective over (k 0..3, n 0..7)
#define A_STRIDE 36
#define B_STRIDE 136
#define A_STG (128 * A_STRIDE)             // floats per stage
#define B_STG (32 * B_STRIDE)
#define STG_F (A_STG + B_STG)
#define GSMEM (2 * STG_F * 4)              // bytes, 2 stages

// ============================================================================
// TF32 mma.sync GEMM: C[M,N] = act(A[M,K] @ W[K,N] + bias), batched over z.
// CTA tile 128x128, 8 warps (4 m x 2 n), warp tile 32x64, mma m16n8k8.
// A and W pre-rounded to tf32 (rna).
// ============================================================================
__global__ __launch_bounds__(256, 2) void gemm_mma(
    const float* __restrict__ A, const float* __restrict__ W,
    const float* __restrict__ bias, float* __restrict__ C,
    int K, int N, int roundOut,
    long long As, long long Ws, long long Cs, long long bs)
{
    extern __shared__ float smf[];
    const uint32_t smem_base = s2u(smf);

    const int tid = threadIdx.x;
    const int wid = tid >> 5, lane = tid & 31;
    const int grp = lane >> 2, tig = lane & 3;
    const int warp_m = wid & 3, warp_n = wid >> 2;   // 4 x 2 warps
    const int e = blockIdx.z;
    const int row0 = blockIdx.x * 128;
    const int col0 = blockIdx.y * 128;
    A += (long long)e * As;
    W += (long long)e * Ws;
    C += (long long)e * Cs;
    bias += (long long)e * bs;

    const int nk = K >> 5;                 // K-chunks of 32

    // ---- cp.async load maps ----
    // A: 128 rows x 32 k. thread: row=tid>>1, half=tid&1, 4x float4.
    const int arow = tid >> 1, ahalf = tid & 1;
    const float* Ag = A + (long long)(row0 + arow) * K;
    // B: 32 k-rows x 128 n. thread: krow=tid>>3, oct=tid&7, 4x float4.
    const int bkrow = tid >> 3, boct = tid & 7;
    const float* Wg = W + (long long)bkrow * N + col0;

    auto loadChunk = [&](int i) {
        const int s = i & 1;
        const uint32_t sA = smem_base + s * (STG_F * 4);
        const uint32_t sB = sA + A_STG * 4;
#pragma unroll
        for (int j = 0; j < 4; j++) {
            const int k4 = ahalf * 4 + j;                       // float4 idx in row
            const uint32_t d = sA + arow * (A_STRIDE * 4) + k4 * 16;
            asm volatile("cp.async.cg.shared.global [%0], [%1], 16;"
                         :: "r"(d), "l"(Ag + i * 32 + k4 * 4) : "memory");
        }
#pragma unroll
        for (int j = 0; j < 4; j++) {
            const int c4 = boct + j * 8;                        // float4 idx in k-row
            const uint32_t d = sB + bkrow * (B_STRIDE * 4) + c4 * 16;
            asm volatile("cp.async.cg.shared.global [%0], [%1], 16;"
                         :: "r"(d), "l"(Wg + (long long)i * 32 * N + c4 * 4) : "memory");
        }
        asm volatile("cp.async.commit_group;" ::: "memory");
    };

    float c[2][8][4];
#pragma unroll
    for (int mt = 0; mt < 2; mt++)
#pragma unroll
        for (int nt = 0; nt < 8; nt++)
#pragma unroll
            for (int q = 0; q < 4; q++) c[mt][nt][q] = 0.f;

    loadChunk(0);

    for (int i = 0; i < nk; i++) {
        if (i + 1 < nk) loadChunk(i + 1);
        if (i + 1 < nk) asm volatile("cp.async.wait_group 1;" ::: "memory");
        else            asm volatile("cp.async.wait_group 0;" ::: "memory");
        __syncthreads();

        const int s = i & 1;
        const uint32_t* AsU = (const uint32_t*)(smf + s * STG_F);
        const uint32_t* BsU = AsU + A_STG;

#pragma unroll
        for (int ks = 0; ks < 4; ks++) {          // 4 x k8 steps per chunk
            uint32_t a[2][4];
#pragma unroll
            for (int mt = 0; mt < 2; mt++) {
                const int rb = warp_m * 32 + mt * 16 + grp;
                const int kb = ks * 8 + tig;
                a[mt][0] = AsU[rb * A_STRIDE + kb];
                a[mt][1] = AsU[(rb + 8) * A_STRIDE + kb];
                a[mt][2] = AsU[rb * A_STRIDE + kb + 4];
                a[mt][3] = AsU[(rb + 8) * A_STRIDE + kb + 4];
            }
            uint32_t b[8][2];
#pragma unroll
            for (int nt = 0; nt < 8; nt++) {
                const int nb = warp_n * 64 + nt * 8 + grp;
                b[nt][0] = BsU[(ks * 8 + tig) * B_STRIDE + nb];
                b[nt][1] = BsU[(ks * 8 + tig + 4) * B_STRIDE + nb];
            }
#pragma unroll
            for (int mt = 0; mt < 2; mt++)
#pragma unroll
                for (int nt = 0; nt < 8; nt++)
                    asm volatile(
                        "mma.sync.aligned.m16n8k8.row.col.f32.tf32.tf32.f32 "
                        "{%0,%1,%2,%3}, {%4,%5,%6,%7}, {%8,%9}, {%0,%1,%2,%3};"
                        : "+f"(c[mt][nt][0]), "+f"(c[mt][nt][1]),
                          "+f"(c[mt][nt][2]), "+f"(c[mt][nt][3])
                        : "r"(a[mt][0]), "r"(a[mt][1]), "r"(a[mt][2]), "r"(a[mt][3]),
                          "r"(b[nt][0]), "r"(b[nt][1]));
        }
        __syncthreads();   // all warps done with stage s before load i+2 overwrites
    }

    // ---- epilogue: c0,c1 -> (row, 2tig); c2,c3 -> (row+8, 2tig) ----
#pragma unroll
    for (int mt = 0; mt < 2; mt++) {
        const int rb = row0 + warp_m * 32 + mt * 16 + grp;
#pragma unroll
        for (int nt = 0; nt < 8; nt++) {
            const int col = col0 + warp_n * 64 + nt * 8 + 2 * tig;
            const float b0 = bias[col], b1 = bias[col + 1];
            float v0 = fmaxf(c[mt][nt][0] + b0, 0.f);
            float v1 = fmaxf(c[mt][nt][1] + b1, 0.f);
            float v2 = fmaxf(c[mt][nt][2] + b0, 0.f);
            float v3 = fmaxf(c[mt][nt][3] + b1, 0.f);
            if (roundOut) {
                v0 = tf32r(v0); v1 = tf32r(v1); v2 = tf32r(v2); v3 = tf32r(v3);
            }
            *(float2*)(C + (long long)rb * N + col)       = make_float2(v0, v1);
            *(float2*)(C + (long long)(rb + 8) * N + col) = make_float2(v2, v3);
        }
    }
}

// ============================================================================
__global__ void round_vec(const float4* __restrict__ in, float4* __restrict__ out, int n4)
{
    const int i = blockIdx.x * 256 + threadIdx.x;
    if (i < n4) {
        float4 v = in[i];
        v.x = tf32r(v.x); v.y = tf32r(v.y); v.z = tf32r(v.z); v.w = tf32r(v.w);
        out[i] = v;
    }
}

// ============================================================================
// Router layer 3 + gumbel softmax (fp32). One thread per row.
// ============================================================================
__global__ __launch_bounds__(256) void router3_kernel(
    const float* __restrict__ hr2, const float* __restrict__ rw3,
    const float* __restrict__ rb3, const float* __restrict__ u,
    float* __restrict__ wout)
{
    __shared__ float w3s[RH2 * EE];
    const int tid = threadIdx.x;
    for (int i = tid; i < RH2 * EE; i += 256) w3s[i] = rw3[i];
    __syncthreads();

    const long long row = (long long)blockIdx.x * 256 + tid;

    float acc[EE];
#pragma unroll
    for (int e = 0; e < EE; e++) acc[e] = rb3[e];

    const float4* hp = (const float4*)(hr2 + row * RH2);
#pragma unroll 8
    for (int k4 = 0; k4 < RH2 / 4; k4++) {
        const float4 h = hp[k4];
        const int k = k4 * 4;
        const float hv[4] = {h.x, h.y, h.z, h.w};
#pragma unroll
        for (int j = 0; j < 4; j++) {
#pragma unroll
            for (int e = 0; e < EE; e++) acc[e] += hv[j] * w3s[(k + j) * EE + e];
        }
    }

    float lg[EE];
    float m = -1e30f;
#pragma unroll
    for (int e = 0; e < EE; e++) {
        float uu = u[row * EE + e];
        uu = fminf(fmaxf(uu, 1e-10f), 1.0f);
        const float g = -logf(-logf(uu) + 1e-10f);
        lg[e] = (acc[e] + g) * (1.0f / 3.0f);
        m = fmaxf(m, lg[e]);
    }
    float s = 0.f;
#pragma unroll
    for (int e = 0; e < EE; e++) { lg[e] = expf(lg[e] - m); s += lg[e]; }
    const float inv = 1.0f / s;
#pragma unroll
    for (int e = 0; e < EE; e++) wout[row * EE + e] = lg[e] * inv;
}

// ============================================================================
// Final: zc = h2 @ ew3 + eb3 -> chart[E,B,2]; z = sum_e w[b,e]*zc. fp32.
// ============================================================================
__global__ __launch_bounds__(128) void out_kernel(
    const float* __restrict__ h2e, const float* __restrict__ ew3,
    const float* __restrict__ eb3, const float* __restrict__ wts,
    float* __restrict__ z, float* __restrict__ chart)
{
    const int warp = threadIdx.x >> 5, lane = threadIdx.x & 31;
    const long long row = (long long)blockIdx.x * 4 + warp;

    float zz0 = 0.f, zz1 = 0.f;
#pragma unroll
    for (int e = 0; e < EE; e++) {
        const float4 h = *(const float4*)(h2e + ((long long)e * BB + row) * HH + lane * 4);
        const float4 wa = *(const float4*)(ew3 + e * (HH * 2) + lane * 8);
        const float4 wb = *(const float4*)(ew3 + e * (HH * 2) + lane * 8 + 4);
        float p0 = h.x * wa.x + h.y * wa.z + h.z * wb.x + h.w * wb.z;
        float p1 = h.x * wa.y + h.y * wa.w + h.z * wb.y + h.w * wb.w;
#pragma unroll
        for (int o = 16; o; o >>= 1) {
            p0 += __shfl_xor_sync(0xffffffffu, p0, o);
            p1 += __shfl_xor_sync(0xffffffffu, p1, o);
        }
        if (lane == 0) {
            p0 += eb3[e * 2 + 0];
            p1 += eb3[e * 2 + 1];
            chart[((long long)e * BB + row) * 2 + 0] = p0;
            chart[((long long)e * BB + row) * 2 + 1] = p1;
            const float w = wts[row * EE + e];
            zz0 += w * p0;
            zz1 += w * p1;
        }
    }
    if (lane == 0) {
        z[row * 2 + 0] = zz0;
        z[row * 2 + 1] = zz1;
    }
}

// ============================================================================
extern "C" void kernel_launch(void* const* d_in, const int* in_sizes, int n_in,
                              void* d_out, int out_size)
{
    const float* x   = (const float*)d_in[0];
    const float* u   = (const float*)d_in[1];
    const float* rw1 = (const float*)d_in[2];
    const float* rb1 = (const float*)d_in[3];
    const float* rw2 = (const float*)d_in[4];
    const float* rb2 = (const float*)d_in[5];
    const float* rw3 = (const float*)d_in[6];
    const float* rb3 = (const float*)d_in[7];
    const float* ew1 = (const float*)d_in[8];
    const float* eb1 = (const float*)d_in[9];
    const float* ew2 = (const float*)d_in[10];
    const float* eb2 = (const float*)d_in[11];
    const float* ew3 = (const float*)d_in[12];
    const float* eb3 = (const float*)d_in[13];

    float* out   = (float*)d_out;
    float* z     = out;                                      // [B, 2]
    float* wts   = out + (size_t)BB * 2;                     // [B, E]
    float* chart = out + (size_t)BB * 2 + (size_t)BB * EE;   // [E, B, 2]

    float *hr1, *hr2, *h1, *h2, *xt, *wr1, *wr2, *we1, *we2;
    cudaGetSymbolAddress((void**)&hr1, g_hr1);
    cudaGetSymbolAddress((void**)&hr2, g_hr2);
    cudaGetSymbolAddress((void**)&h1, g_h1);
    cudaGetSymbolAddress((void**)&h2, g_h2);
    cudaGetSymbolAddress((void**)&xt, g_xt);
    cudaGetSymbolAddress((void**)&wr1, g_wr1);
    cudaGetSymbolAddress((void**)&wr2, g_wr2);
    cudaGetSymbolAddress((void**)&we1, g_we1);
    cudaGetSymbolAddress((void**)&we2, g_we2);

    cudaFuncSetAttribute(gemm_mma, cudaFuncAttributeMaxDynamicSharedMemorySize, GSMEM);

    // ---- prep: tf32-round x and all GEMM weights (layouts unchanged) ----
    round_vec<<<(BB * DD / 4 + 255) / 256, 256>>>((const float4*)x, (float4*)xt, BB * DD / 4);
    round_vec<<<(DD * RH1 / 4 + 255) / 256, 256>>>((const float4*)rw1, (float4*)wr1, DD * RH1 / 4);
    round_vec<<<(RH1 * RH2 / 4 + 255) / 256, 256>>>((const float4*)rw2, (float4*)wr2, RH1 * RH2 / 4);
    round_vec<<<(EE * DD * HH / 4 + 255) / 256, 256>>>((const float4*)ew1, (float4*)we1, EE * DD * HH / 4);
    round_vec<<<(EE * HH * HH / 4 + 255) / 256, 256>>>((const float4*)ew2, (float4*)we2, EE * HH * HH / 4);

    // ---- router L1: [B,512]@[512,256] -> relu -> hr1 (rounded) ----
    gemm_mma<<<dim3(BB / 128, RH1 / 128, 1), 256, GSMEM>>>(
        xt, wr1, rb1, hr1, DD, RH1, 1, 0, 0, 0, 0);
    // ---- router L2: [B,256]@[256,128] -> relu -> hr2 (fp32) ----
    gemm_mma<<<dim3(BB / 128, 1, 1), 256, GSMEM>>>(
        hr1, wr2, rb2, hr2, RH1, RH2, 0, 0, 0, 0, 0);
    // ---- router L3 + gumbel softmax -> weights ----
    router3_kernel<<<BB / 256, 256>>>(hr2, rw3, rb3, u, wts);

    // ---- experts L1 (batched over E): [B,512]@[512,128] -> relu -> h1 ----
    gemm_mma<<<dim3(BB / 128, 1, EE), 256, GSMEM>>>(
        xt, we1, eb1, h1, DD, HH, 1,
        0, (long long)DD * HH, (long long)BB * HH, HH);
    // ---- experts L2: h1@[128,128] -> relu -> h2 (fp32) ----
    gemm_mma<<<dim3(BB / 128, 1, EE), 256, GSMEM>>>(
        h1, we2, eb2, h2, HH, HH, 0,
        (long long)BB * HH, (long long)HH * HH, (long long)BB * HH, HH);

    // ---- experts L3 + weighted combine -> chart + z ----
    out_kernel<<<BB / 4, 128>>>(h2, eb3 ? ew3 : ew3, eb3, wts, z, chart);
}

// round 7
// speedup vs baseline: 2.7214x; 1.4645x over previous
#include <cuda_runtime.h>
#include <cstdint>

#define BB 32768
#define DD 512
#define EE 10
#define HH 128
#define RH1 256
#define RH2 128

// ---- scratch (static __device__ globals: allocation-guard safe) ----
__device__ float g_hr1[(size_t)BB * RH1];          // router L1 out (tf32-rounded)
__device__ float g_xt[(size_t)BB * DD];            // tf32-rounded x
__device__ float g_wr1[(size_t)DD * RH1];          // tf32-rounded weights
__device__ float g_wr2[(size_t)RH1 * RH2];
__device__ float g_we1[(size_t)EE * DD * HH];
__device__ float g_we2[(size_t)EE * HH * HH];

__device__ __forceinline__ float tf32r(float f) {
    float r; asm("cvt.rna.tf32.f32 %0, %1;" : "=f"(r) : "f"(f)); return r;
}
__device__ __forceinline__ uint32_t s2u(const void* p) {
    uint32_t a;
    asm("{ .reg .u64 t; cvta.to.shared.u64 t, %1; cvt.u32.u64 %0, t; }" : "=r"(a) : "l"(p));
    return a;
}

// ---- smem geometry (floats). Conflict-free strides: 36%32=4, 136%32=8, 132%32=4.
#define A_STRIDE 36
#define B_STRIDE 136
#define A_STG (128 * A_STRIDE)             // 4608 floats
#define B_STG (32 * B_STRIDE)              // 4352 floats
#define STG_F (A_STG + B_STG)              // 8960 floats per stage
#define GSMEM (2 * STG_F * 4)              // 71680 B (2-stage ring)
#define H1_STRIDE 132                      // h1 smem buffer stride
#define L2B_OFF (2 * STG_F)                // float offset of L2 B-stage ring
#define MEGA_SMEM ((L2B_OFF + 2 * B_STG) * 4)   // 106496 B

#define CPA(dst, src) \
    asm volatile("cp.async.cg.shared.global [%0], [%1], 16;" :: "r"(dst), "l"(src) : "memory")
#define CPC() asm volatile("cp.async.commit_group;" ::: "memory")
#define CPW1() asm volatile("cp.async.wait_group 1;" ::: "memory")
#define CPW0() asm volatile("cp.async.wait_group 0;" ::: "memory")

// mma.sync m16n8k8 tf32 macro on accumulator c[4]
#define MMA8(cc, a0, a1, a2, a3, b0, b1) \
    asm volatile("mma.sync.aligned.m16n8k8.row.col.f32.tf32.tf32.f32 " \
                 "{%0,%1,%2,%3}, {%4,%5,%6,%7}, {%8,%9}, {%0,%1,%2,%3};" \
                 : "+f"(cc[0]), "+f"(cc[1]), "+f"(cc[2]), "+f"(cc[3]) \
                 : "r"(a0), "r"(a1), "r"(a2), "r"(a3), "r"(b0), "r"(b1))

// ============================================================================
// Generic TF32 mma GEMM (proven in R6): C = act(A @ W + bias), batched over z.
// Used only for router L1 here.
// ============================================================================
__global__ __launch_bounds__(256, 2) void gemm_mma(
    const float* __restrict__ A, const float* __restrict__ W,
    const float* __restrict__ bias, float* __restrict__ C,
    int K, int N, int roundOut)
{
    extern __shared__ float smf[];
    const uint32_t smem_base = s2u(smf);
    const int tid = threadIdx.x;
    const int wid = tid >> 5, lane = tid & 31;
    const int grp = lane >> 2, tig = lane & 3;
    const int warp_m = wid & 3, warp_n = wid >> 2;
    const int row0 = blockIdx.x * 128;
    const int col0 = blockIdx.y * 128;

    const int nk = K >> 5;
    const int arow = tid >> 1, ahalf = tid & 1;
    const float* Ag = A + (long long)(row0 + arow) * K;
    const int bkrow = tid >> 3, boct = tid & 7;
    const float* Wg = W + (long long)bkrow * N + col0;

    auto loadChunk = [&](int i) {
        const uint32_t sA = smem_base + (i & 1) * (STG_F * 4);
        const uint32_t sB = sA + A_STG * 4;
#pragma unroll
        for (int j = 0; j < 4; j++) {
            const int k4 = ahalf * 4 + j;
            CPA(sA + arow * (A_STRIDE * 4) + k4 * 16, Ag + i * 32 + k4 * 4);
        }
#pragma unroll
        for (int j = 0; j < 4; j++) {
            const int c4 = boct + j * 8;
            CPA(sB + bkrow * (B_STRIDE * 4) + c4 * 16, Wg + (long long)i * 32 * N + c4 * 4);
        }
        CPC();
    };

    float c[2][8][4];
#pragma unroll
    for (int mt = 0; mt < 2; mt++)
#pragma unroll
        for (int nt = 0; nt < 8; nt++)
#pragma unroll
            for (int q = 0; q < 4; q++) c[mt][nt][q] = 0.f;

    loadChunk(0);
    for (int i = 0; i < nk; i++) {
        if (i + 1 < nk) { loadChunk(i + 1); CPW1(); } else CPW0();
        __syncthreads();
        const uint32_t* AsU = (const uint32_t*)(smf + (i & 1) * STG_F);
        const uint32_t* BsU = AsU + A_STG;
#pragma unroll
        for (int ks = 0; ks < 4; ks++) {
            uint32_t a[2][4];
#pragma unroll
            for (int mt = 0; mt < 2; mt++) {
                const int rb = warp_m * 32 + mt * 16 + grp;
                const int kb = ks * 8 + tig;
                a[mt][0] = AsU[rb * A_STRIDE + kb];
                a[mt][1] = AsU[(rb + 8) * A_STRIDE + kb];
                a[mt][2] = AsU[rb * A_STRIDE + kb + 4];
                a[mt][3] = AsU[(rb + 8) * A_STRIDE + kb + 4];
            }
            uint32_t b[8][2];
#pragma unroll
            for (int nt = 0; nt < 8; nt++) {
                const int nb = warp_n * 64 + nt * 8 + grp;
                b[nt][0] = BsU[(ks * 8 + tig) * B_STRIDE + nb];
                b[nt][1] = BsU[(ks * 8 + tig + 4) * B_STRIDE + nb];
            }
#pragma unroll
            for (int mt = 0; mt < 2; mt++)
#pragma unroll
                for (int nt = 0; nt < 8; nt++)
                    MMA8(c[mt][nt], a[mt][0], a[mt][1], a[mt][2], a[mt][3],
                         b[nt][0], b[nt][1]);
        }
        __syncthreads();
    }

#pragma unroll
    for (int mt = 0; mt < 2; mt++) {
        const int rb = row0 + warp_m * 32 + mt * 16 + grp;
#pragma unroll
        for (int nt = 0; nt < 8; nt++) {
            const int col = col0 + warp_n * 64 + nt * 8 + 2 * tig;
            const float b0 = bias[col], b1 = bias[col + 1];
            float v0 = fmaxf(c[mt][nt][0] + b0, 0.f);
            float v1 = fmaxf(c[mt][nt][1] + b1, 0.f);
            float v2 = fmaxf(c[mt][nt][2] + b0, 0.f);
            float v3 = fmaxf(c[mt][nt][3] + b1, 0.f);
            if (roundOut) { v0 = tf32r(v0); v1 = tf32r(v1); v2 = tf32r(v2); v3 = tf32r(v3); }
            *(float2*)(C + (long long)rb * N + col)       = make_float2(v0, v1);
            *(float2*)(C + (long long)(rb + 8) * N + col) = make_float2(v2, v3);
        }
    }
}

// ============================================================================
// Fused router L2 + L3 + gumbel softmax. Block = 128 rows, full N=128.
// logits reduced via smem atomics; weights written directly.
// ============================================================================
__global__ __launch_bounds__(256, 2) void fused_router(
    const float* __restrict__ hr1, const float* __restrict__ wr2,
    const float* __restrict__ rb2, const float* __restrict__ rw3,
    const float* __restrict__ rb3, const float* __restrict__ u,
    float* __restrict__ wout)
{
    extern __shared__ float smf[];
    __shared__ float lgs[128 * EE];
    __shared__ float w3s[RH2 * EE];
    __shared__ float rb3s[EE];
    __shared__ float rb2s[RH2];
    const uint32_t smem_base = s2u(smf);
    const int tid = threadIdx.x;
    const int wid = tid >> 5, lane = tid & 31;
    const int grp = lane >> 2, tig = lane & 3;
    const int warp_m = wid & 3, warp_n = wid >> 2;
    const int row0 = blockIdx.x * 128;

    for (int i = tid; i < RH2 * EE; i += 256) { w3s[i] = rw3[i]; lgs[i] = 0.f; }
    if (tid < EE)  rb3s[tid] = rb3[tid];
    if (tid < RH2) rb2s[tid] = rb2[tid];

    const int arow = tid >> 1, ahalf = tid & 1;
    const float* Ag = hr1 + (long long)(row0 + arow) * RH1;
    const int bkrow = tid >> 3, boct = tid & 7;

    auto loadChunk = [&](int i) {
        const uint32_t sA = smem_base + (i & 1) * (STG_F * 4);
        const uint32_t sB = sA + A_STG * 4;
#pragma unroll
        for (int j = 0; j < 4; j++) {
            const int k4 = ahalf * 4 + j;
            CPA(sA + arow * (A_STRIDE * 4) + k4 * 16, Ag + i * 32 + k4 * 4);
        }
#pragma unroll
        for (int j = 0; j < 4; j++) {
            const int c4 = boct + j * 8;
            CPA(sB + bkrow * (B_STRIDE * 4) + c4 * 16,
                wr2 + (long long)(i * 32 + bkrow) * RH2 + c4 * 4);
        }
        CPC();
    };

    float c[2][8][4];
#pragma unroll
    for (int mt = 0; mt < 2; mt++)
#pragma unroll
        for (int nt = 0; nt < 8; nt++)
#pragma unroll
            for (int q = 0; q < 4; q++) c[mt][nt][q] = 0.f;

    loadChunk(0);
    const int nk = RH1 >> 5;           // 8
    for (int i = 0; i < nk; i++) {
        if (i + 1 < nk) { loadChunk(i + 1); CPW1(); } else CPW0();
        __syncthreads();
        const uint32_t* AsU = (const uint32_t*)(smf + (i & 1) * STG_F);
        const uint32_t* BsU = AsU + A_STG;
#pragma unroll
        for (int ks = 0; ks < 4; ks++) {
            uint32_t a[2][4];
#pragma unroll
            for (int mt = 0; mt < 2; mt++) {
                const int rb = warp_m * 32 + mt * 16 + grp;
                const int kb = ks * 8 + tig;
                a[mt][0] = AsU[rb * A_STRIDE + kb];
                a[mt][1] = AsU[(rb + 8) * A_STRIDE + kb];
                a[mt][2] = AsU[rb * A_STRIDE + kb + 4];
                a[mt][3] = AsU[(rb + 8) * A_STRIDE + kb + 4];
            }
            uint32_t b[8][2];
#pragma unroll
            for (int nt = 0; nt < 8; nt++) {
                const int nb = warp_n * 64 + nt * 8 + grp;
                b[nt][0] = BsU[(ks * 8 + tig) * B_STRIDE + nb];
                b[nt][1] = BsU[(ks * 8 + tig + 4) * B_STRIDE + nb];
            }
#pragma unroll
            for (int mt = 0; mt < 2; mt++)
#pragma unroll
                for (int nt = 0; nt < 8; nt++)
                    MMA8(c[mt][nt], a[mt][0], a[mt][1], a[mt][2], a[mt][3],
                         b[nt][0], b[nt][1]);
        }
        __syncthreads();
    }

    // logits partials: relu(h) @ rw3
#pragma unroll
    for (int mt = 0; mt < 2; mt++) {
        float pl0[EE], pl1[EE];
#pragma unroll
        for (int e = 0; e < EE; e++) { pl0[e] = 0.f; pl1[e] = 0.f; }
#pragma unroll
        for (int nt = 0; nt < 8; nt++) {
            const int col = warp_n * 64 + nt * 8 + 2 * tig;
            const float b0 = rb2s[col], b1 = rb2s[col + 1];
            const float v0 = fmaxf(c[mt][nt][0] + b0, 0.f);
            const float v1 = fmaxf(c[mt][nt][1] + b1, 0.f);
            const float v2 = fmaxf(c[mt][nt][2] + b0, 0.f);
            const float v3 = fmaxf(c[mt][nt][3] + b1, 0.f);
#pragma unroll
            for (int e = 0; e < EE; e++) {
                const float w0 = w3s[col * EE + e], w1 = w3s[(col + 1) * EE + e];
                pl0[e] += v0 * w0 + v1 * w1;
                pl1[e] += v2 * w0 + v3 * w1;
            }
        }
        const int r = warp_m * 32 + mt * 16 + grp;
#pragma unroll
        for (int e = 0; e < EE; e++) {
            atomicAdd(&lgs[r * EE + e], pl0[e]);
            atomicAdd(&lgs[(r + 8) * EE + e], pl1[e]);
        }
    }
    __syncthreads();

    if (tid < 128) {
        const long long row = row0 + tid;
        float lg[EE];
        float m = -1e30f;
#pragma unroll
        for (int e = 0; e < EE; e++) {
            float uu = u[row * EE + e];
            uu = fminf(fmaxf(uu, 1e-10f), 1.0f);
            const float g = -logf(-logf(uu) + 1e-10f);
            lg[e] = (lgs[tid * EE + e] + rb3s[e] + g) * (1.0f / 3.0f);
            m = fmaxf(m, lg[e]);
        }
        float s = 0.f;
#pragma unroll
        for (int e = 0; e < EE; e++) { lg[e] = expf(lg[e] - m); s += lg[e]; }
        const float inv = 1.0f / s;
#pragma unroll
        for (int e = 0; e < EE; e++) wout[row * EE + e] = lg[e] * inv;
    }
}

// ============================================================================
// Expert megakernel: per 128-row block, loop e=0..9:
//   L1 GEMM (x@we1, K=512) -> relu+round -> smem h1 buffer ->
//   L2 GEMM (h1@we2, K=128, A from smem) -> L3 (H->2) + chart + z accumulate.
// h1/h2 never touch DRAM.
// ============================================================================
__global__ __launch_bounds__(256, 2) void expert_mega(
    const float* __restrict__ xt, const float* __restrict__ we1,
    const float* __restrict__ eb1, const float* __restrict__ we2,
    const float* __restrict__ eb2, const float* __restrict__ ew3,
    const float* __restrict__ eb3, const float* __restrict__ wts,
    float* __restrict__ z, float* __restrict__ chart)
{
    extern __shared__ float smf[];
    __shared__ float zcs[256];       // zc reduction [128 rows][2]
    __shared__ float zacc[256];      // z accumulator [128 rows][2]
    __shared__ float ew3s[256];      // ew3[e] slice [128][2]
    __shared__ float eb1s[128];
    __shared__ float eb2s[128];
    const uint32_t smem_base = s2u(smf);
    const int tid = threadIdx.x;
    const int wid = tid >> 5, lane = tid & 31;
    const int grp = lane >> 2, tig = lane & 3;
    const int warp_m = wid & 3, warp_n = wid >> 2;
    const int row0 = blockIdx.x * 128;

    zacc[tid] = 0.f;

    const int arow = tid >> 1, ahalf = tid & 1;
    const float* Ag = xt + (long long)(row0 + arow) * DD;
    const int bkrow = tid >> 3, boct = tid & 7;

    auto loadL1 = [&](int e, int i) {
        const uint32_t sA = smem_base + (i & 1) * (STG_F * 4);
        const uint32_t sB = sA + A_STG * 4;
#pragma unroll
        for (int j = 0; j < 4; j++) {
            const int k4 = ahalf * 4 + j;
            CPA(sA + arow * (A_STRIDE * 4) + k4 * 16, Ag + i * 32 + k4 * 4);
        }
        const float* Wg = we1 + ((long long)e * DD + i * 32 + bkrow) * HH;
#pragma unroll
        for (int j = 0; j < 4; j++) {
            const int c4 = boct + j * 8;
            CPA(sB + bkrow * (B_STRIDE * 4) + c4 * 16, Wg + c4 * 4);
        }
        CPC();
    };
    auto loadL2B = [&](int e, int kc) {
        const uint32_t sB = smem_base + L2B_OFF * 4 + (kc & 1) * (B_STG * 4);
        const float* Wg = we2 + ((long long)e * HH + kc * 32 + bkrow) * HH;
#pragma unroll
        for (int j = 0; j < 4; j++) {
            const int c4 = boct + j * 8;
            CPA(sB + bkrow * (B_STRIDE * 4) + c4 * 16, Wg + c4 * 4);
        }
        CPC();
    };

    float c[2][8][4];

    loadL1(0, 0);   // prefetch very first chunk
    for (int e = 0; e < EE; e++) {
        if (tid < 128) eb1s[tid] = eb1[e * HH + tid];
#pragma unroll
        for (int mt = 0; mt < 2; mt++)
#pragma unroll
            for (int nt = 0; nt < 8; nt++)
#pragma unroll
                for (int q = 0; q < 4; q++) c[mt][nt][q] = 0.f;

        // ---- L1 mainloop: 16 chunks (chunk 0 already in flight) ----
        for (int i = 0; i < 16; i++) {
            if (i + 1 < 16) { loadL1(e, i + 1); CPW1(); } else CPW0();
            __syncthreads();
            const uint32_t* AsU = (const uint32_t*)(smf + (i & 1) * STG_F);
            const uint32_t* BsU = AsU + A_STG;
#pragma unroll
            for (int ks = 0; ks < 4; ks++) {
                uint32_t a[2][4];
#pragma unroll
                for (int mt = 0; mt < 2; mt++) {
                    const int rb = warp_m * 32 + mt * 16 + grp;
                    const int kb = ks * 8 + tig;
                    a[mt][0] = AsU[rb * A_STRIDE + kb];
                    a[mt][1] = AsU[(rb + 8) * A_STRIDE + kb];
                    a[mt][2] = AsU[rb * A_STRIDE + kb + 4];
                    a[mt][3] = AsU[(rb + 8) * A_STRIDE + kb + 4];
                }
                uint32_t b[8][2];
#pragma unroll
                for (int nt = 0; nt < 8; nt++) {
                    const int nb = warp_n * 64 + nt * 8 + grp;
                    b[nt][0] = BsU[(ks * 8 + tig) * B_STRIDE + nb];
                    b[nt][1] = BsU[(ks * 8 + tig + 4) * B_STRIDE + nb];
                }
#pragma unroll
                for (int mt = 0; mt < 2; mt++)
#pragma unroll
                    for (int nt = 0; nt < 8; nt++)
                        MMA8(c[mt][nt], a[mt][0], a[mt][1], a[mt][2], a[mt][3],
                             b[nt][0], b[nt][1]);
            }
            __syncthreads();
        }

        loadL2B(e, 0);   // prefetch L2 B chunk 0 (disjoint smem region)

        // ---- h1 = round(relu(c + eb1)) -> smem h1buf (stride 132) ----
#pragma unroll
        for (int mt = 0; mt < 2; mt++) {
            const int r = warp_m * 32 + mt * 16 + grp;
#pragma unroll
            for (int nt = 0; nt < 8; nt++) {
                const int col = warp_n * 64 + nt * 8 + 2 * tig;
                const float b0 = eb1s[col], b1 = eb1s[col + 1];
                smf[r * H1_STRIDE + col]           = tf32r(fmaxf(c[mt][nt][0] + b0, 0.f));
                smf[r * H1_STRIDE + col + 1]       = tf32r(fmaxf(c[mt][nt][1] + b1, 0.f));
                smf[(r + 8) * H1_STRIDE + col]     = tf32r(fmaxf(c[mt][nt][2] + b0, 0.f));
                smf[(r + 8) * H1_STRIDE + col + 1] = tf32r(fmaxf(c[mt][nt][3] + b1, 0.f));
            }
        }
        __syncthreads();

        // ---- L2 mainloop: 4 chunks, A from h1buf ----
#pragma unroll
        for (int mt = 0; mt < 2; mt++)
#pragma unroll
            for (int nt = 0; nt < 8; nt++)
#pragma unroll
                for (int q = 0; q < 4; q++) c[mt][nt][q] = 0.f;

        const uint32_t* H1U = (const uint32_t*)smf;
        for (int kc = 0; kc < 4; kc++) {
            if (kc + 1 < 4) { loadL2B(e, kc + 1); CPW1(); } else CPW0();
            __syncthreads();
            const uint32_t* BsU = (const uint32_t*)(smf + L2B_OFF + (kc & 1) * B_STG);
#pragma unroll
            for (int ks = 0; ks < 4; ks++) {
                uint32_t a[2][4];
#pragma unroll
                for (int mt = 0; mt < 2; mt++) {
                    const int rb = warp_m * 32 + mt * 16 + grp;
                    const int kb = kc * 32 + ks * 8 + tig;
                    a[mt][0] = H1U[rb * H1_STRIDE + kb];
                    a[mt][1] = H1U[(rb + 8) * H1_STRIDE + kb];
                    a[mt][2] = H1U[rb * H1_STRIDE + kb + 4];
                    a[mt][3] = H1U[(rb + 8) * H1_STRIDE + kb + 4];
                }
                uint32_t b[8][2];
#pragma unroll
                for (int nt = 0; nt < 8; nt++) {
                    const int nb = warp_n * 64 + nt * 8 + grp;
                    b[nt][0] = BsU[(ks * 8 + tig) * B_STRIDE + nb];
                    b[nt][1] = BsU[(ks * 8 + tig + 4) * B_STRIDE + nb];
                }
#pragma unroll
                for (int mt = 0; mt < 2; mt++)
#pragma unroll
                    for (int nt = 0; nt < 8; nt++)
                        MMA8(c[mt][nt], a[mt][0], a[mt][1], a[mt][2], a[mt][3],
                             b[nt][0], b[nt][1]);
            }
            __syncthreads();
        }

        if (e + 1 < EE) loadL1(e + 1, 0);   // prefetch next expert's first chunk

        // ---- L3: zc = relu(c + eb2) @ ew3[e] + eb3 ; chart, z acc ----
        ew3s[tid < 256 ? tid : 0] = ew3[(long long)e * 256 + tid];
        if (tid < 128) eb2s[tid] = eb2[e * HH + tid];
        zcs[tid] = 0.f;
        __syncthreads();

#pragma unroll
        for (int mt = 0; mt < 2; mt++) {
            float p00 = 0.f, p01 = 0.f, p10 = 0.f, p11 = 0.f;
#pragma unroll
            for (int nt = 0; nt < 8; nt++) {
                const int col = warp_n * 64 + nt * 8 + 2 * tig;
                const float b0 = eb2s[col], b1 = eb2s[col + 1];
                const float v0 = fmaxf(c[mt][nt][0] + b0, 0.f);
                const float v1 = fmaxf(c[mt][nt][1] + b1, 0.f);
                const float v2 = fmaxf(c[mt][nt][2] + b0, 0.f);
                const float v3 = fmaxf(c[mt][nt][3] + b1, 0.f);
                const float w00 = ew3s[col * 2],       w01 = ew3s[col * 2 + 1];
                const float w10 = ew3s[(col + 1) * 2], w11 = ew3s[(col + 1) * 2 + 1];
                p00 += v0 * w00 + v1 * w10;  p01 += v0 * w01 + v1 * w11;
                p10 += v2 * w00 + v3 * w10;  p11 += v2 * w01 + v3 * w11;
            }
            const int r = warp_m * 32 + mt * 16 + grp;
            atomicAdd(&zcs[r * 2],           p00);
            atomicAdd(&zcs[r * 2 + 1],       p01);
            atomicAdd(&zcs[(r + 8) * 2],     p10);
            atomicAdd(&zcs[(r + 8) * 2 + 1], p11);
        }
        __syncthreads();

        if (tid < 128) {
            const long long row = row0 + tid;
            const float zc0 = zcs[tid * 2]     + eb3[e * 2];
            const float zc1 = zcs[tid * 2 + 1] + eb3[e * 2 + 1];
            *(float2*)(chart + ((long long)e * BB + row) * 2) = make_float2(zc0, zc1);
            const float w = wts[row * EE + e];
            zacc[tid * 2]     += w * zc0;
            zacc[tid * 2 + 1] += w * zc1;
        }
        __syncthreads();
    }

    if (tid < 128) {
        const long long row = row0 + tid;
        *(float2*)(z + row * 2) = make_float2(zacc[tid * 2], zacc[tid * 2 + 1]);
    }
}

// ============================================================================
__global__ void round_vec(const float4* __restrict__ in, float4* __restrict__ out, int n4)
{
    const int i = blockIdx.x * 256 + threadIdx.x;
    if (i < n4) {
        float4 v = in[i];
        v.x = tf32r(v.x); v.y = tf32r(v.y); v.z = tf32r(v.z); v.w = tf32r(v.w);
        out[i] = v;
    }
}

// ============================================================================
extern "C" void kernel_launch(void* const* d_in, const int* in_sizes, int n_in,
                              void* d_out, int out_size)
{
    const float* x   = (const float*)d_in[0];
    const float* u   = (const float*)d_in[1];
    const float* rw1 = (const float*)d_in[2];
    const float* rb1 = (const float*)d_in[3];
    const float* rw2 = (const float*)d_in[4];
    const float* rb2 = (const float*)d_in[5];
    const float* rw3 = (const float*)d_in[6];
    const float* rb3 = (const float*)d_in[7];
    const float* ew1 = (const float*)d_in[8];
    const float* eb1 = (const float*)d_in[9];
    const float* ew2 = (const float*)d_in[10];
    const float* eb2 = (const float*)d_in[11];
    const float* ew3 = (const float*)d_in[12];
    const float* eb3 = (const float*)d_in[13];

    float* out   = (float*)d_out;
    float* z     = out;                                      // [B, 2]
    float* wts   = out + (size_t)BB * 2;                     // [B, E]
    float* chart = out + (size_t)BB * 2 + (size_t)BB * EE;   // [E, B, 2]

    float *hr1, *xt, *wr1, *wr2, *we1, *we2;
    cudaGetSymbolAddress((void**)&hr1, g_hr1);
    cudaGetSymbolAddress((void**)&xt, g_xt);
    cudaGetSymbolAddress((void**)&wr1, g_wr1);
    cudaGetSymbolAddress((void**)&wr2, g_wr2);
    cudaGetSymbolAddress((void**)&we1, g_we1);
    cudaGetSymbolAddress((void**)&we2, g_we2);

    cudaFuncSetAttribute(gemm_mma, cudaFuncAttributeMaxDynamicSharedMemorySize, GSMEM);
    cudaFuncSetAttribute(fused_router, cudaFuncAttributeMaxDynamicSharedMemorySize, GSMEM);
    cudaFuncSetAttribute(expert_mega, cudaFuncAttributeMaxDynamicSharedMemorySize, MEGA_SMEM);

    // ---- prep: tf32-round (rna) x and GEMM weights ----
    round_vec<<<(BB * DD / 4 + 255) / 256, 256>>>((const float4*)x, (float4*)xt, BB * DD / 4);
    round_vec<<<(DD * RH1 / 4 + 255) / 256, 256>>>((const float4*)rw1, (float4*)wr1, DD * RH1 / 4);
    round_vec<<<(RH1 * RH2 / 4 + 255) / 256, 256>>>((const float4*)rw2, (float4*)wr2, RH1 * RH2 / 4);
    round_vec<<<(EE * DD * HH / 4 + 255) / 256, 256>>>((const float4*)ew1, (float4*)we1, EE * DD * HH / 4);
    round_vec<<<(EE * HH * HH / 4 + 255) / 256, 256>>>((const float4*)ew2, (float4*)we2, EE * HH * HH / 4);

    // ---- router L1: [B,512]@[512,256] -> relu -> hr1 (rounded) ----
    gemm_mma<<<dim3(BB / 128, RH1 / 128, 1), 256, GSMEM>>>(xt, wr1, rb1, hr1, DD, RH1, 1);
    // ---- router L2+L3+gumbel -> wts ----
    fused_router<<<BB / 128, 256, GSMEM>>>(hr1, wr2, rb2, rw3, rb3, u, wts);
    // ---- experts fully fused -> chart + z ----
    expert_mega<<<BB / 128, 256, MEGA_SMEM>>>(xt, we1, eb1, we2, eb2, ew3, eb3, wts, z, chart);
}

// round 8
// speedup vs baseline: 2.9078x; 1.0685x over previous
#include <cuda_runtime.h>
#include <cstdint>

#define BB 32768
#define DD 512
#define EE 10
#define HH 128
#define RH1 256
#define RH2 128

// ---- scratch (static __device__ globals: allocation-guard safe) ----
__device__ float g_hr1[(size_t)BB * RH1];          // router L1 out (tf32-rounded)
__device__ float g_xt[(size_t)BB * DD];            // tf32-rounded x
__device__ float g_wr1[(size_t)DD * RH1];          // tf32-rounded weights
__device__ float g_wr2[(size_t)RH1 * RH2];
__device__ float g_we1[(size_t)EE * DD * HH];
__device__ float g_we2[(size_t)EE * HH * HH];

__device__ __forceinline__ float tf32r(float f) {
    float r; asm("cvt.rna.tf32.f32 %0, %1;" : "=f"(r) : "f"(f)); return r;
}
__device__ __forceinline__ uint32_t s2u(const void* p) {
    uint32_t a;
    asm("{ .reg .u64 t; cvta.to.shared.u64 t, %1; cvt.u32.u64 %0, t; }" : "=r"(a) : "l"(p));
    return a;
}

// ---- smem geometry (floats). Conflict-free strides: 36%32=4, 136%32=8, 132%32=4.
#define A_STRIDE 36
#define B_STRIDE 136
#define A_STG (128 * A_STRIDE)             // 4608 floats
#define B_STG (32 * B_STRIDE)              // 4352 floats
#define STG_F (A_STG + B_STG)              // 8960 floats per stage
#define AUX_OFF (2 * STG_F)                // aux region: L2-B ring / router lgs+w3s
#define H1_STRIDE 132                      // h1 smem buffer stride (overlays ring)
#define MEGA_SMEM ((AUX_OFF + 2 * B_STG) * 4)   // 106496 B

#define CPA(dst, src) \
    asm volatile("cp.async.cg.shared.global [%0], [%1], 16;" :: "r"(dst), "l"(src) : "memory")
#define CPC() asm volatile("cp.async.commit_group;" ::: "memory")
#define CPW0() asm volatile("cp.async.wait_group 0;" ::: "memory")

#define MMA8(cc, a0, a1, a2, a3, b0, b1) \
    asm volatile("mma.sync.aligned.m16n8k8.row.col.f32.tf32.tf32.f32 " \
                 "{%0,%1,%2,%3}, {%4,%5,%6,%7}, {%8,%9}, {%0,%1,%2,%3};" \
                 : "+f"(cc[0]), "+f"(cc[1]), "+f"(cc[2]), "+f"(cc[3]) \
                 : "r"(a0), "r"(a1), "r"(a2), "r"(a3), "r"(b0), "r"(b1))

// One 32-k chunk of 128x128 CTA-tile MMA work. AsU: A rows (stride astride),
// BsU: B k-rows (stride B_STRIDE). Warp tile 32x64 (mt=2, nt=8).
__device__ __forceinline__ void mma_chunk(
    const uint32_t* __restrict__ AsU, int astride,
    const uint32_t* __restrict__ BsU,
    float (&c)[2][8][4], int warp_m, int warp_n, int grp, int tig)
{
#pragma unroll
    for (int ks = 0; ks < 4; ks++) {
        uint32_t a[2][4];
#pragma unroll
        for (int mt = 0; mt < 2; mt++) {
            const int rb = warp_m * 32 + mt * 16 + grp;
            const int kb = ks * 8 + tig;
            a[mt][0] = AsU[rb * astride + kb];
            a[mt][1] = AsU[(rb + 8) * astride + kb];
            a[mt][2] = AsU[rb * astride + kb + 4];
            a[mt][3] = AsU[(rb + 8) * astride + kb + 4];
        }
        uint32_t b[8][2];
#pragma unroll
        for (int nt = 0; nt < 8; nt++) {
            const int nb = warp_n * 64 + nt * 8 + grp;
            b[nt][0] = BsU[(ks * 8 + tig) * B_STRIDE + nb];
            b[nt][1] = BsU[(ks * 8 + tig + 4) * B_STRIDE + nb];
        }
#pragma unroll
        for (int mt = 0; mt < 2; mt++)
#pragma unroll
            for (int nt = 0; nt < 8; nt++)
                MMA8(c[mt][nt], a[mt][0], a[mt][1], a[mt][2], a[mt][3],
                     b[nt][0], b[nt][1]);
    }
}

// ============================================================================
// Megakernel. grid = (256 row-blocks, 3 roles).
//   role 0: router L1 (2 col-tiles, via g_hr1) + L2 + logits + gumbel -> wts
//   role 1: experts 0..4  -> chart
//   role 2: experts 5..9  -> chart
// Single-bar 2-stage cp.async pipelines: [wait0][bar][issue next][compute].
// ============================================================================
__global__ __launch_bounds__(256, 2) void mega(
    const float* __restrict__ xt, const float* __restrict__ wr1,
    const float* __restrict__ rb1, const float* __restrict__ wr2,
    const float* __restrict__ rb2, const float* __restrict__ rw3,
    const float* __restrict__ rb3, const float* __restrict__ u,
    const float* __restrict__ we1, const float* __restrict__ eb1,
    const float* __restrict__ we2, const float* __restrict__ eb2,
    const float* __restrict__ ew3, const float* __restrict__ eb3,
    float* __restrict__ hr1, float* __restrict__ wts, float* __restrict__ chart)
{
    extern __shared__ float smf[];
    __shared__ float zcs[256];        // expert L3 reduction [128 rows][2]
    __shared__ float ew3s[256];       // ew3[e] slice [128][2]
    __shared__ float eb1s[128];
    __shared__ float eb2s[128];

    const uint32_t smem_base = s2u(smf);
    const int tid = threadIdx.x;
    const int wid = tid >> 5, lane = tid & 31;
    const int grp = lane >> 2, tig = lane & 3;
    const int warp_m = wid & 3, warp_n = wid >> 2;
    const int row0 = blockIdx.x * 128;
    const int role = blockIdx.y;

    // cp.async staging maps (shared by all loaders)
    const int arow = tid >> 1, ahalf = tid & 1;     // A: row, float4-half
    const int bkrow = tid >> 3, boct = tid & 7;     // B: k-row, float4-oct

    float c[2][8][4];

    if (role == 0) {
        // ---------------- ROUTER ----------------
        float* lgs = smf + AUX_OFF;               // [128][EE] logits accum
        float* w3s = lgs + 128 * EE;              // [RH2][EE]
        for (int i = tid; i < RH2 * EE; i += 256) { w3s[i] = rw3[i]; lgs[i] = 0.f; }

        const float* Ag = xt + (long long)(row0 + arow) * DD;

        // --- R1: two 128-col tiles, K=512 ---
        for (int ct = 0; ct < 2; ct++) {
            auto loadR1 = [&](int i) {
                const uint32_t sA = smem_base + (i & 1) * (STG_F * 4);
                const uint32_t sB = sA + A_STG * 4;
#pragma unroll
                for (int j = 0; j < 4; j++) {
                    const int k4 = ahalf * 4 + j;
                    CPA(sA + arow * (A_STRIDE * 4) + k4 * 16, Ag + i * 32 + k4 * 4);
                }
                const float* Wg = wr1 + (long long)(i * 32 + bkrow) * RH1 + ct * 128;
#pragma unroll
                for (int j = 0; j < 4; j++) {
                    const int c4 = boct + j * 8;
                    CPA(sB + bkrow * (B_STRIDE * 4) + c4 * 16, Wg + c4 * 4);
                }
                CPC();
            };
#pragma unroll
            for (int mt = 0; mt < 2; mt++)
#pragma unroll
                for (int nt = 0; nt < 8; nt++)
#pragma unroll
                    for (int q = 0; q < 4; q++) c[mt][nt][q] = 0.f;

            loadR1(0);
            for (int i = 0; i < 16; i++) {
                CPW0();
                __syncthreads();
                if (i + 1 < 16) loadR1(i + 1);
                const uint32_t* AsU = (const uint32_t*)(smf + (i & 1) * STG_F);
                mma_chunk(AsU, A_STRIDE, AsU + A_STG, c, warp_m, warp_n, grp, tig);
            }
            __syncthreads();    // ring reuse by next ct / R2

            // epilogue: hr1[:, ct*128 ..] = round(relu(c + rb1))
#pragma unroll
            for (int mt = 0; mt < 2; mt++) {
                const int rb = row0 + warp_m * 32 + mt * 16 + grp;
#pragma unroll
                for (int nt = 0; nt < 8; nt++) {
                    const int col = ct * 128 + warp_n * 64 + nt * 8 + 2 * tig;
                    const float b0 = rb1[col], b1 = rb1[col + 1];
                    const float v0 = tf32r(fmaxf(c[mt][nt][0] + b0, 0.f));
                    const float v1 = tf32r(fmaxf(c[mt][nt][1] + b1, 0.f));
                    const float v2 = tf32r(fmaxf(c[mt][nt][2] + b0, 0.f));
                    const float v3 = tf32r(fmaxf(c[mt][nt][3] + b1, 0.f));
                    *(float2*)(hr1 + (long long)rb * RH1 + col)       = make_float2(v0, v1);
                    *(float2*)(hr1 + (long long)(rb + 8) * RH1 + col) = make_float2(v2, v3);
                }
            }
        }
        __syncthreads();   // hr1 STGs visible to all threads before cp.async reads

        // --- R2: K=256, N=128, A = hr1 rows ---
        const float* Ag2 = hr1 + (long long)(row0 + arow) * RH1;
        auto loadR2 = [&](int i) {
            const uint32_t sA = smem_base + (i & 1) * (STG_F * 4);
            const uint32_t sB = sA + A_STG * 4;
#pragma unroll
            for (int j = 0; j < 4; j++) {
                const int k4 = ahalf * 4 + j;
                CPA(sA + arow * (A_STRIDE * 4) + k4 * 16, Ag2 + i * 32 + k4 * 4);
            }
            const float* Wg = wr2 + (long long)(i * 32 + bkrow) * RH2;
#pragma unroll
            for (int j = 0; j < 4; j++) {
                const int c4 = boct + j * 8;
                CPA(sB + bkrow * (B_STRIDE * 4) + c4 * 16, Wg + c4 * 4);
            }
            CPC();
        };
#pragma unroll
        for (int mt = 0; mt < 2; mt++)
#pragma unroll
            for (int nt = 0; nt < 8; nt++)
#pragma unroll
                for (int q = 0; q < 4; q++) c[mt][nt][q] = 0.f;

        loadR2(0);
        for (int i = 0; i < 8; i++) {
            CPW0();
            __syncthreads();
            if (i + 1 < 8) loadR2(i + 1);
            const uint32_t* AsU = (const uint32_t*)(smf + (i & 1) * STG_F);
            mma_chunk(AsU, A_STRIDE, AsU + A_STG, c, warp_m, warp_n, grp, tig);
        }
        __syncthreads();

        // --- logits partials: relu(c + rb2) @ rw3, smem atomics ---
#pragma unroll
        for (int mt = 0; mt < 2; mt++) {
            float pl0[EE], pl1[EE];
#pragma unroll
            for (int e = 0; e < EE; e++) { pl0[e] = 0.f; pl1[e] = 0.f; }
#pragma unroll
            for (int nt = 0; nt < 8; nt++) {
                const int col = warp_n * 64 + nt * 8 + 2 * tig;
                const float b0 = rb2[col], b1 = rb2[col + 1];
                const float v0 = fmaxf(c[mt][nt][0] + b0, 0.f);
                const float v1 = fmaxf(c[mt][nt][1] + b1, 0.f);
                const float v2 = fmaxf(c[mt][nt][2] + b0, 0.f);
                const float v3 = fmaxf(c[mt][nt][3] + b1, 0.f);
#pragma unroll
                for (int e = 0; e < EE; e++) {
                    const float w0 = w3s[col * EE + e], w1 = w3s[(col + 1) * EE + e];
                    pl0[e] += v0 * w0 + v1 * w1;
                    pl1[e] += v2 * w0 + v3 * w1;
                }
            }
            const int r = warp_m * 32 + mt * 16 + grp;
#pragma unroll
            for (int e = 0; e < EE; e++) {
                atomicAdd(&lgs[r * EE + e], pl0[e]);
                atomicAdd(&lgs[(r + 8) * EE + e], pl1[e]);
            }
        }
        __syncthreads();

        // --- gumbel softmax ---
        if (tid < 128) {
            const long long row = row0 + tid;
            float lg[EE];
            float m = -1e30f;
#pragma unroll
            for (int e = 0; e < EE; e++) {
                float uu = u[row * EE + e];
                uu = fminf(fmaxf(uu, 1e-10f), 1.0f);
                const float g = -logf(-logf(uu) + 1e-10f);
                lg[e] = (lgs[tid * EE + e] + rb3[e] + g) * (1.0f / 3.0f);
                m = fmaxf(m, lg[e]);
            }
            float s = 0.f;
#pragma unroll
            for (int e = 0; e < EE; e++) { lg[e] = expf(lg[e] - m); s += lg[e]; }
            const float inv = 1.0f / s;
#pragma unroll
            for (int e = 0; e < EE; e++) wts[row * EE + e] = lg[e] * inv;
        }
        return;
    }

    // ---------------- EXPERTS (5 per block) ----------------
    const int e0 = 5 * (role - 1);
    const float* Ag = xt + (long long)(row0 + arow) * DD;

    auto loadL1 = [&](int e, int i) {
        const uint32_t sA = smem_base + (i & 1) * (STG_F * 4);
        const uint32_t sB = sA + A_STG * 4;
#pragma unroll
        for (int j = 0; j < 4; j++) {
            const int k4 = ahalf * 4 + j;
            CPA(sA + arow * (A_STRIDE * 4) + k4 * 16, Ag + i * 32 + k4 * 4);
        }
        const float* Wg = we1 + ((long long)e * DD + i * 32 + bkrow) * HH;
#pragma unroll
        for (int j = 0; j < 4; j++) {
            const int c4 = boct + j * 8;
            CPA(sB + bkrow * (B_STRIDE * 4) + c4 * 16, Wg + c4 * 4);
        }
        CPC();
    };
    auto loadL2B = [&](int e, int kc) {
        const uint32_t sB = smem_base + AUX_OFF * 4 + (kc & 1) * (B_STG * 4);
        const float* Wg = we2 + ((long long)e * HH + kc * 32 + bkrow) * HH;
#pragma unroll
        for (int j = 0; j < 4; j++) {
            const int c4 = boct + j * 8;
            CPA(sB + bkrow * (B_STRIDE * 4) + c4 * 16, Wg + c4 * 4);
        }
        CPC();
    };

    loadL1(e0, 0);
    for (int e = e0; e < e0 + 5; e++) {
        if (tid < 128) eb1s[tid] = eb1[e * HH + tid];
#pragma unroll
        for (int mt = 0; mt < 2; mt++)
#pragma unroll
            for (int nt = 0; nt < 8; nt++)
#pragma unroll
                for (int q = 0; q < 4; q++) c[mt][nt][q] = 0.f;

        // --- L1: K=512, 16 chunks ---
        for (int i = 0; i < 16; i++) {
            CPW0();
            __syncthreads();
            if (i + 1 < 16) loadL1(e, i + 1);
            const uint32_t* AsU = (const uint32_t*)(smf + (i & 1) * STG_F);
            mma_chunk(AsU, A_STRIDE, AsU + A_STG, c, warp_m, warp_n, grp, tig);
        }
        loadL2B(e, 0);      // aux region: safe (prev expert drained)
        __syncthreads();    // all done reading ring before h1 overlay write

        // --- h1 = round(relu(c + eb1)) -> smem (overlays ring) ---
#pragma unroll
        for (int mt = 0; mt < 2; mt++) {
            const int r = warp_m * 32 + mt * 16 + grp;
#pragma unroll
            for (int nt = 0; nt < 8; nt++) {
                const int col = warp_n * 64 + nt * 8 + 2 * tig;
                const float b0 = eb1s[col], b1 = eb1s[col + 1];
                smf[r * H1_STRIDE + col]           = tf32r(fmaxf(c[mt][nt][0] + b0, 0.f));
                smf[r * H1_STRIDE + col + 1]       = tf32r(fmaxf(c[mt][nt][1] + b1, 0.f));
                smf[(r + 8) * H1_STRIDE + col]     = tf32r(fmaxf(c[mt][nt][2] + b0, 0.f));
                smf[(r + 8) * H1_STRIDE + col + 1] = tf32r(fmaxf(c[mt][nt][3] + b1, 0.f));
            }
        }

        // --- L2: K=128, 4 chunks, A from h1 smem ---
#pragma unroll
        for (int mt = 0; mt < 2; mt++)
#pragma unroll
            for (int nt = 0; nt < 8; nt++)
#pragma unroll
                for (int q = 0; q < 4; q++) c[mt][nt][q] = 0.f;

        const uint32_t* H1U = (const uint32_t*)smf;
        for (int kc = 0; kc < 4; kc++) {
            CPW0();
            __syncthreads();    // also orders h1 writes before first reads
            if (kc + 1 < 4) loadL2B(e, kc + 1);
            const uint32_t* BsU = (const uint32_t*)(smf + AUX_OFF + (kc & 1) * B_STG);
            mma_chunk(H1U + kc * 32, H1_STRIDE, BsU, c, warp_m, warp_n, grp, tig);
        }
        __syncthreads();        // all done reading h1 before ring reuse

        if (e + 1 < e0 + 5) loadL1(e + 1, 0);

        // --- L3: zc = relu(c + eb2) @ ew3[e] -> chart ---
        ew3s[tid] = ew3[(long long)e * 256 + tid];
        if (tid < 128) eb2s[tid] = eb2[e * HH + tid];
        zcs[tid] = 0.f;
        __syncthreads();

#pragma unroll
        for (int mt = 0; mt < 2; mt++) {
            float p00 = 0.f, p01 = 0.f, p10 = 0.f, p11 = 0.f;
#pragma unroll
            for (int nt = 0; nt < 8; nt++) {
                const int col = warp_n * 64 + nt * 8 + 2 * tig;
                const float b0 = eb2s[col], b1 = eb2s[col + 1];
                const float v0 = fmaxf(c[mt][nt][0] + b0, 0.f);
                const float v1 = fmaxf(c[mt][nt][1] + b1, 0.f);
                const float v2 = fmaxf(c[mt][nt][2] + b0, 0.f);
                const float v3 = fmaxf(c[mt][nt][3] + b1, 0.f);
                const float w00 = ew3s[col * 2],       w01 = ew3s[col * 2 + 1];
                const float w10 = ew3s[(col + 1) * 2], w11 = ew3s[(col + 1) * 2 + 1];
                p00 += v0 * w00 + v1 * w10;  p01 += v0 * w01 + v1 * w11;
                p10 += v2 * w00 + v3 * w10;  p11 += v2 * w01 + v3 * w11;
            }
            const int r = warp_m * 32 + mt * 16 + grp;
            atomicAdd(&zcs[r * 2],           p00);
            atomicAdd(&zcs[r * 2 + 1],       p01);
            atomicAdd(&zcs[(r + 8) * 2],     p10);
            atomicAdd(&zcs[(r + 8) * 2 + 1], p11);
        }
        __syncthreads();

        if (tid < 128) {
            const long long row = row0 + tid;
            const float zc0 = zcs[tid * 2]     + eb3[e * 2];
            const float zc1 = zcs[tid * 2 + 1] + eb3[e * 2 + 1];
            *(float2*)(chart + ((long long)e * BB + row) * 2) = make_float2(zc0, zc1);
        }
        __syncthreads();   // zcs/ew3s/eb1s reuse next expert
    }
}

// ============================================================================
// z[b] = sum_e wts[b,e] * chart[e,b,:]
// ============================================================================
__global__ __launch_bounds__(256) void zfinal(
    const float* __restrict__ chart, const float* __restrict__ wts,
    float* __restrict__ z)
{
    const long long b = (long long)blockIdx.x * 256 + threadIdx.x;
    float z0 = 0.f, z1 = 0.f;
#pragma unroll
    for (int e = 0; e < EE; e++) {
        const float2 zc = *(const float2*)(chart + ((long long)e * BB + b) * 2);
        const float w = wts[b * EE + e];
        z0 += w * zc.x;
        z1 += w * zc.y;
    }
    *(float2*)(z + b * 2) = make_float2(z0, z1);
}

// ============================================================================
// All operand rounding (rna -> tf32) in one launch.
// ============================================================================
#define S0 (BB * DD / 4)
#define S1 (DD * RH1 / 4)
#define S2 (RH1 * RH2 / 4)
#define S3 (EE * DD * HH / 4)
#define S4 (EE * HH * HH / 4)
#define STOT (S0 + S1 + S2 + S3 + S4)

__global__ __launch_bounds__(256) void round_all(
    const float4* __restrict__ x, const float4* __restrict__ rw1,
    const float4* __restrict__ rw2, const float4* __restrict__ ew1,
    const float4* __restrict__ ew2,
    float4* __restrict__ xt, float4* __restrict__ wr1, float4* __restrict__ wr2,
    float4* __restrict__ we1, float4* __restrict__ we2)
{
    long long i = (long long)blockIdx.x * 256 + threadIdx.x;
    const float4* src; float4* dst; long long off;
    if      (i < S0)                    { src = x;   dst = xt;  off = i; }
    else if (i < S0 + S1)               { src = rw1; dst = wr1; off = i - S0; }
    else if (i < S0 + S1 + S2)          { src = rw2; dst = wr2; off = i - S0 - S1; }
    else if (i < S0 + S1 + S2 + S3)     { src = ew1; dst = we1; off = i - S0 - S1 - S2; }
    else if (i < STOT)                  { src = ew2; dst = we2; off = i - S0 - S1 - S2 - S3; }
    else return;
    float4 v = src[off];
    v.x = tf32r(v.x); v.y = tf32r(v.y); v.z = tf32r(v.z); v.w = tf32r(v.w);
    dst[off] = v;
}

// ============================================================================
extern "C" void kernel_launch(void* const* d_in, const int* in_sizes, int n_in,
                              void* d_out, int out_size)
{
    const float* x   = (const float*)d_in[0];
    const float* u   = (const float*)d_in[1];
    const float* rw1 = (const float*)d_in[2];
    const float* rb1 = (const float*)d_in[3];
    const float* rw2 = (const float*)d_in[4];
    const float* rb2 = (const float*)d_in[5];
    const float* rw3 = (const float*)d_in[6];
    const float* rb3 = (const float*)d_in[7];
    const float* ew1 = (const float*)d_in[8];
    const float* eb1 = (const float*)d_in[9];
    const float* ew2 = (const float*)d_in[10];
    const float* eb2 = (const float*)d_in[11];
    const float* ew3 = (const float*)d_in[12];
    const float* eb3 = (const float*)d_in[13];

    float* out   = (float*)d_out;
    float* z     = out;                                      // [B, 2]
    float* wts   = out + (size_t)BB * 2;                     // [B, E]
    float* chart = out + (size_t)BB * 2 + (size_t)BB * EE;   // [E, B, 2]

    float *hr1, *xt, *wr1, *wr2, *we1, *we2;
    cudaGetSymbolAddress((void**)&hr1, g_hr1);
    cudaGetSymbolAddress((void**)&xt, g_xt);
    cudaGetSymbolAddress((void**)&wr1, g_wr1);
    cudaGetSymbolAddress((void**)&wr2, g_wr2);
    cudaGetSymbolAddress((void**)&we1, g_we1);
    cudaGetSymbolAddress((void**)&we2, g_we2);

    cudaFuncSetAttribute(mega, cudaFuncAttributeMaxDynamicSharedMemorySize, MEGA_SMEM);

    round_all<<<(STOT + 255) / 256, 256>>>(
        (const float4*)x, (const float4*)rw1, (const float4*)rw2,
        (const float4*)ew1, (const float4*)ew2,
        (float4*)xt, (float4*)wr1, (float4*)wr2, (float4*)we1, (float4*)we2);

    mega<<<dim3(BB / 128, 3), 256, MEGA_SMEM>>>(
        xt, wr1, rb1, wr2, rb2, rw3, rb3, u,
        we1, eb1, we2, eb2, ew3, eb3, hr1, wts, chart);

    zfinal<<<BB / 256, 256>>>(chart, wts, z);
}